// round 10
// baseline (speedup 1.0000x reference)
#include <cuda_runtime.h>
#include <cuda_bf16.h>
#include <cstdint>

// Problem constants
#define BB   2
#define TT   4096
#define DD   512
#define HH   8
#define DHH  64
#define MTOT (BB*TT)          // 8192
#define WSZ  (DD*DD)

// Scratch (allocation-free __device__ globals)
__device__ float g_Q[BB*HH*TT*DHH];                 // (bh, t, dh) fp32
__device__ __nv_bfloat16 g_Kh[BB*HH*TT*DHH];        // (bh, t, dh) bf16 hi
__device__ __nv_bfloat16 g_Kl[BB*HH*TT*DHH];        // lo
__device__ __nv_bfloat16 g_Vth[BB*HH*DHH*TT];       // V TRANSPOSED: (bh, dh, t) hi
__device__ __nv_bfloat16 g_Vtl[BB*HH*DHH*TT];       // lo
__device__ __nv_bfloat16 g_Xh[MTOT*DD];             // x split hi (m, k)
__device__ __nv_bfloat16 g_Xl[MTOT*DD];
__device__ __nv_bfloat16 g_Wh[4*WSZ];               // Wq,Wk,Wv,Wo split hi (k, n)
__device__ __nv_bfloat16 g_Wl[4*WSZ];
__device__ __nv_bfloat16 g_Oh[MTOT*DD];             // attention out split hi (m, D)
__device__ __nv_bfloat16 g_Ol[MTOT*DD];
__device__ uint64_t g_maskbits[TT * (TT / 64)];      // bit k of word (r, w): mask[r][w*64+k]
__device__ int g_mask_mode;                          // 0=1B, 1=2B, 2=4B elements

// ---------------------------------------------------------------------------
// Helpers
// ---------------------------------------------------------------------------
__device__ __forceinline__ float bf16_round(float x) {
    return __bfloat162float(__float2bfloat16(x));
}
// returns bf16x2 with 'a' in low half (first element), 'b' in high half
__device__ __forceinline__ uint32_t pack_bf16x2(float a, float b) {
    uint32_t r;
    asm("cvt.rn.satfinite.bf16x2.f32 %0, %1, %2;" : "=r"(r) : "f"(b), "f"(a));
    return r;
}
// D += A * B  (m16n8k16, row.col, bf16 in, f32 acc)
__device__ __forceinline__ void mma16816(float* d, const uint32_t* a, uint32_t b0, uint32_t b1) {
    asm volatile("mma.sync.aligned.m16n8k16.row.col.f32.bf16.bf16.f32 "
        "{%0,%1,%2,%3}, {%4,%5,%6,%7}, {%8,%9}, {%0,%1,%2,%3};"
        : "+f"(d[0]), "+f"(d[1]), "+f"(d[2]), "+f"(d[3])
        : "r"(a[0]), "r"(a[1]), "r"(a[2]), "r"(a[3]), "r"(b0), "r"(b1));
}
__device__ __forceinline__ uint32_t smem_u32(const void* p) {
    uint32_t a;
    asm("{ .reg .u64 t; cvta.to.shared.u64 t, %1; cvt.u32.u64 %0, t; }" : "=r"(a) : "l"(p));
    return a;
}
__device__ __forceinline__ void cpa16(uint32_t d, const void* s) {
    asm volatile("cp.async.cg.shared.global [%0], [%1], 16;" :: "r"(d), "l"(s));
}
__device__ __forceinline__ void cpa_commit() {
    asm volatile("cp.async.commit_group;" ::: "memory");
}
template<int N> __device__ __forceinline__ void cpa_wait() {
    asm volatile("cp.async.wait_group %0;" :: "n"(N) : "memory");
}
__device__ __forceinline__ void ldsm4(uint32_t* d, uint32_t a) {
    asm volatile("ldmatrix.sync.aligned.m8n8.x4.shared.b16 {%0,%1,%2,%3}, [%4];"
        : "=r"(d[0]), "=r"(d[1]), "=r"(d[2]), "=r"(d[3]) : "r"(a));
}
__device__ __forceinline__ void ldsm4t(uint32_t* d, uint32_t a) {
    asm volatile("ldmatrix.sync.aligned.m8n8.x4.trans.shared.b16 {%0,%1,%2,%3}, [%4];"
        : "=r"(d[0]), "=r"(d[1]), "=r"(d[2]), "=r"(d[3]) : "r"(a));
}

// ---------------------------------------------------------------------------
// Mask dtype detection (validated)
// ---------------------------------------------------------------------------
__device__ __forceinline__ bool hw_ok(uint32_t h) {
    return h == 0u || h == 1u || h == 0x3F80u;
}
__global__ void detect_mask_kernel(const uint32_t* __restrict__ m)
{
    int lane = threadIdx.x;
    bool w4 = true, w2 = true;
    for (int i = lane; i < 1024; i += 32) {
        uint32_t w = m[i];
        if (!(w == 0u || w == 1u || w == 0x3F800000u)) w4 = false;
        if (!(hw_ok(w & 0xFFFFu) && hw_ok(w >> 16)))   w2 = false;
    }
    unsigned b4 = __ballot_sync(0xffffffffu, w4);
    unsigned b2 = __ballot_sync(0xffffffffu, w2);
    if (lane == 0)
        g_mask_mode = (b4 == 0xffffffffu) ? 2 : ((b2 == 0xffffffffu) ? 1 : 0);
}

// ---------------------------------------------------------------------------
// Mask bit-packing (validated)
// ---------------------------------------------------------------------------
__global__ void pack_mask_kernel(const void* __restrict__ mask_raw)
{
    int idx = blockIdx.x * 256 + threadIdx.x;      // 0 .. 262143
    int row = idx >> 6;
    int wi  = idx & 63;
    const int mode = g_mask_mode;
    uint64_t bits = 0;
    if (mode == 2) {
        const uint4* p = (const uint4*)((const uint32_t*)mask_raw + (size_t)row * TT + wi * 64);
#pragma unroll
        for (int w = 0; w < 16; w++) {
            uint4 v = p[w];
            uint64_t f = (uint64_t)((v.x != 0u) | ((v.y != 0u) << 1)
                                  | ((v.z != 0u) << 2) | ((v.w != 0u) << 3));
            bits |= f << (w * 4);
        }
    } else if (mode == 1) {
        const uint16_t* p = (const uint16_t*)mask_raw + (size_t)row * TT + wi * 64;
#pragma unroll
        for (int k = 0; k < 64; k++)
            bits |= (uint64_t)(p[k] != 0) << k;
    } else {
        const uint8_t* p = (const uint8_t*)mask_raw + (size_t)row * TT + wi * 64;
#pragma unroll
        for (int k = 0; k < 64; k++)
            bits |= (uint64_t)(p[k] != 0) << k;
    }
    g_maskbits[idx] = bits;
}

// ---------------------------------------------------------------------------
// Split kernels: fp32 -> bf16 hi/lo
// ---------------------------------------------------------------------------
__global__ void split_x_kernel(const float* __restrict__ x)
{
    size_t i = ((size_t)blockIdx.x * 256 + threadIdx.x) * 4;
    float4 v = *(const float4*)(x + i);
    float h0 = bf16_round(v.x), h1 = bf16_round(v.y);
    float h2 = bf16_round(v.z), h3 = bf16_round(v.w);
    *(uint2*)&g_Xh[i] = make_uint2(pack_bf16x2(h0, h1), pack_bf16x2(h2, h3));
    *(uint2*)&g_Xl[i] = make_uint2(pack_bf16x2(v.x - h0, v.y - h1), pack_bf16x2(v.z - h2, v.w - h3));
}

__global__ void split_w_kernel(const float* __restrict__ W0, const float* __restrict__ W1,
                               const float* __restrict__ W2, const float* __restrict__ W3)
{
    const float* W = (blockIdx.y == 0) ? W0 : (blockIdx.y == 1) ? W1 : (blockIdx.y == 2) ? W2 : W3;
    size_t off = (size_t)blockIdx.y * WSZ;
    size_t i = ((size_t)blockIdx.x * 256 + threadIdx.x) * 4;
    float4 v = *(const float4*)(W + i);
    float h0 = bf16_round(v.x), h1 = bf16_round(v.y);
    float h2 = bf16_round(v.z), h3 = bf16_round(v.w);
    *(uint2*)&g_Wh[off + i] = make_uint2(pack_bf16x2(h0, h1), pack_bf16x2(h2, h3));
    *(uint2*)&g_Wl[off + i] = make_uint2(pack_bf16x2(v.x - h0, v.y - h1), pack_bf16x2(v.z - h2, v.w - h3));
}

// ---------------------------------------------------------------------------
// Shared GEMM core (unchanged, validated round 9)
// ---------------------------------------------------------------------------
#define SMA_SZ (2*2*128*40)
#define SMB_SZ (2*2*32*72)
#define GEMM_SMEM ((SMA_SZ + SMB_SZ) * 2)   // bytes = 59392

__device__ __forceinline__ void gemm_core(
    const __nv_bfloat16* __restrict__ Ah, const __nv_bfloat16* __restrict__ Al,
    const __nv_bfloat16* __restrict__ Bh, const __nv_bfloat16* __restrict__ Bl,
    int m0, int n0, float c[2][4][4])
{
    extern __shared__ __nv_bfloat16 sm[];
    const int tid = threadIdx.x;
    const int wid = tid >> 5, lane = tid & 31;
    const int wr = wid >> 1, wc = wid & 1;
    const int quad = lane >> 3, r8 = lane & 7;

#pragma unroll
    for (int mt = 0; mt < 2; mt++)
#pragma unroll
        for (int nt = 0; nt < 4; nt++)
#pragma unroll
            for (int e = 0; e < 4; e++) c[mt][nt][e] = 0.f;

    auto preload = [&](int buf, int k0) {
#pragma unroll
        for (int i = 0; i < 6; i++) {
            int ch = tid + i * 256;            // 0..1535
            if (ch < 1024) {                   // A: 2 x 128 rows x 4 chunks
                int h = ch >> 9, rem = ch & 511;
                int row = rem >> 2, kc = rem & 3;
                uint32_t dst = smem_u32(&sm[((buf * 2 + h) * 128 + row) * 40 + kc * 8]);
                cpa16(dst, (h ? Al : Ah) + (size_t)(m0 + row) * DD + k0 + kc * 8);
            } else {                           // B: 2 x 32 rows x 8 chunks
                int d2 = ch - 1024;
                int h = d2 >> 8, rem = d2 & 255;
                int row = rem >> 3, nc = rem & 7;
                uint32_t dst = smem_u32(&sm[SMA_SZ + ((buf * 2 + h) * 32 + row) * 72 + nc * 8]);
                cpa16(dst, (h ? Bl : Bh) + (size_t)(k0 + row) * DD + n0 + nc * 8);
            }
        }
        cpa_commit();
    };

    preload(0, 0);
    for (int s = 0; s < 16; s++) {
        if (s + 1 < 16) { preload((s + 1) & 1, (s + 1) * 32); cpa_wait<1>(); }
        else            { cpa_wait<0>(); }
        __syncthreads();
        const int buf = s & 1;

#pragma unroll
        for (int chunk = 0; chunk < 2; chunk++) {
            uint32_t ah0[4], al0[4], ah1[4], al1[4];
            int arow0 = wr * 32 + (quad & 1) * 8 + r8;
            int acol  = chunk * 16 + (quad >> 1) * 8;
            ldsm4(ah0, smem_u32(&sm[((buf * 2 + 0) * 128 + arow0) * 40 + acol]));
            ldsm4(al0, smem_u32(&sm[((buf * 2 + 1) * 128 + arow0) * 40 + acol]));
            ldsm4(ah1, smem_u32(&sm[((buf * 2 + 0) * 128 + arow0 + 16) * 40 + acol]));
            ldsm4(al1, smem_u32(&sm[((buf * 2 + 1) * 128 + arow0 + 16) * 40 + acol]));
#pragma unroll
            for (int ntp = 0; ntp < 2; ntp++) {
                uint32_t bhf[4], blf[4];
                int brow = chunk * 16 + (quad & 1) * 8 + r8;
                int bcol = wc * 32 + ntp * 16 + (quad >> 1) * 8;
                ldsm4t(bhf, smem_u32(&sm[SMA_SZ + ((buf * 2 + 0) * 32 + brow) * 72 + bcol]));
                ldsm4t(blf, smem_u32(&sm[SMA_SZ + ((buf * 2 + 1) * 32 + brow) * 72 + bcol]));
#pragma unroll
                for (int half = 0; half < 2; half++) {
                    int nt = ntp * 2 + half;
                    uint32_t b0 = bhf[half * 2], b1 = bhf[half * 2 + 1];
                    uint32_t bl0 = blf[half * 2], bl1 = blf[half * 2 + 1];
                    mma16816(c[0][nt], ah0, b0, b1);
                    mma16816(c[0][nt], al0, b0, b1);
                    mma16816(c[0][nt], ah0, bl0, bl1);
                    mma16816(c[1][nt], ah1, b0, b1);
                    mma16816(c[1][nt], al1, b0, b1);
                    mma16816(c[1][nt], ah1, bl0, bl1);
                }
            }
        }
        __syncthreads();
    }
}

// ---------------------------------------------------------------------------
// QKV projection via HMMA (unchanged, validated round 9)
// ---------------------------------------------------------------------------
__global__ void __launch_bounds__(256, 2)
gemm_qkv_mma(const float* __restrict__ bq, const float* __restrict__ bk,
             const float* __restrict__ bv)
{
    const int mode = blockIdx.z;
    const int m0 = blockIdx.y * 128, n0 = blockIdx.x * 64;
    const float* bias = (mode == 0) ? bq : (mode == 1) ? bk : bv;

    float c[2][4][4];
    gemm_core(g_Xh, g_Xl, g_Wh + (size_t)mode * WSZ, g_Wl + (size_t)mode * WSZ, m0, n0, c);

    const int tid = threadIdx.x, wid = tid >> 5, lane = tid & 31;
    const int wr = wid >> 1, wc = wid & 1, g = lane >> 2, tg = lane & 3;

#pragma unroll
    for (int mt = 0; mt < 2; mt++) {
#pragma unroll
        for (int nt = 0; nt < 4; nt++) {
            int n = n0 + wc * 32 + nt * 8 + tg * 2;
            int h = n >> 6, dh = n & 63;
            float b0v = bias[n], b1v = bias[n + 1];
#pragma unroll
            for (int e = 0; e < 2; e++) {
                int m = m0 + wr * 32 + mt * 16 + g + e * 8;
                int b = m >> 12, t = m & 4095;
                float v0 = c[mt][nt][e * 2 + 0] + b0v;
                float v1 = c[mt][nt][e * 2 + 1] + b1v;
                size_t bhh = (size_t)b * HH + h;
                if (mode == 0) {
                    *(float2*)&g_Q[(bhh * TT + t) * DHH + dh] = make_float2(v0, v1);
                } else if (mode == 1) {
                    float h0 = bf16_round(v0), h1 = bf16_round(v1);
                    size_t idx = (bhh * TT + t) * DHH + dh;
                    *(uint32_t*)&g_Kh[idx] = pack_bf16x2(h0, h1);
                    *(uint32_t*)&g_Kl[idx] = pack_bf16x2(v0 - h0, v1 - h1);
                } else {
                    float h0 = bf16_round(v0), h1 = bf16_round(v1);
                    size_t i0 = (bhh * DHH + dh) * TT + t;
                    size_t i1 = (bhh * DHH + dh + 1) * TT + t;
                    g_Vth[i0] = __float2bfloat16(h0);
                    g_Vtl[i0] = __float2bfloat16(v0 - h0);
                    g_Vth[i1] = __float2bfloat16(h1);
                    g_Vtl[i1] = __float2bfloat16(v1 - h1);
                }
            }
        }
    }
}

// ---------------------------------------------------------------------------
// Output projection via HMMA (unchanged, validated round 9)
// ---------------------------------------------------------------------------
__global__ void __launch_bounds__(256, 2)
gemm_out_mma(const float* __restrict__ bo, float* __restrict__ out)
{
    const int m0 = blockIdx.y * 128, n0 = blockIdx.x * 64;
    float c[2][4][4];
    gemm_core(g_Oh, g_Ol, g_Wh + 3 * (size_t)WSZ, g_Wl + 3 * (size_t)WSZ, m0, n0, c);

    const int tid = threadIdx.x, wid = tid >> 5, lane = tid & 31;
    const int wr = wid >> 1, wc = wid & 1, g = lane >> 2, tg = lane & 3;

#pragma unroll
    for (int mt = 0; mt < 2; mt++) {
#pragma unroll
        for (int nt = 0; nt < 4; nt++) {
            int n = n0 + wc * 32 + nt * 8 + tg * 2;
            float b0v = bo[n], b1v = bo[n + 1];
#pragma unroll
            for (int e = 0; e < 2; e++) {
                int m = m0 + wr * 32 + mt * 16 + g + e * 8;
                float v0 = c[mt][nt][e * 2 + 0] + b0v;
                float v1 = c[mt][nt][e * 2 + 1] + b1v;
                *(float2*)&out[(size_t)m * DD + n] = make_float2(v0, v1);
            }
        }
    }
}

// ---------------------------------------------------------------------------
// Kernel 2: flash attention, restructured:
// BM=128 (8 warps, 16 q-rows each), BN=64 keys/tile, cp.async double-buffered
// K/V staging, ldmatrix.x4 fragment loads.  Numerics identical to round 8/9.
// smem: [2 buf][4 arr: Kh,Kl,Vh,Vl][64 rows x SROW], SROW=72 b16.
// ---------------------------------------------------------------------------
#define SROW 72
#define ARRSZ (64 * SROW)                    // b16 units per array
#define FLASH_SMEM (2 * 4 * ARRSZ * 2)       // 73728 bytes

__global__ void __launch_bounds__(256, 1)
flash_attn_mma(int dummy)
{
    extern __shared__ __nv_bfloat16 fsm[];

    const int tid  = threadIdx.x;
    const int wid  = tid >> 5;
    const int lane = tid & 31;
    const int g    = lane >> 2;      // group row 0..7
    const int tg   = lane & 3;       // thread-in-group 0..3
    const int bh   = blockIdx.x;     // 0..15
    const int q0   = blockIdx.y * 128;
    const int r0   = q0 + wid * 16;  // this warp's first q row

    const __nv_bfloat16* gKh = g_Kh + (size_t)bh * TT * DHH;
    const __nv_bfloat16* gKl = g_Kl + (size_t)bh * TT * DHH;
    const __nv_bfloat16* gVh = g_Vth + (size_t)bh * DHH * TT;
    const __nv_bfloat16* gVl = g_Vtl + (size_t)bh * DHH * TT;

    // smem base addresses (bytes) for [buf][arr]
    uint32_t smb = smem_u32(fsm);

    // ldmatrix lane addressing: tile = lane>>3 (0..3)
    //  d0: rows +0, k +0 | d1: rows +0, k +8 | d2: rows +8, k +0 | d3: rows +8, k +8
    const int rowsel = (lane & 7) + ((lane >> 4) << 3);
    const int kadd   = ((lane >> 3) & 1) * 8;
    const uint32_t lane_off = (uint32_t)(rowsel * SROW + kadd) * 2;   // bytes

    // ---- load Q A-fragments (hi/lo), scaled by 1/8 ----
    uint32_t qh[4][4], ql[4][4];
    {
        const float* q0p = g_Q + ((size_t)bh * TT + r0 + g) * DHH;
        const float* q8p = q0p + 8 * DHH;
#pragma unroll
        for (int ks = 0; ks < 4; ks++) {
            int c0 = ks * 16 + tg * 2;
            int c1 = c0 + 8;
            float2 v00 = *(const float2*)(q0p + c0);
            float2 v10 = *(const float2*)(q8p + c0);
            float2 v01 = *(const float2*)(q0p + c1);
            float2 v11 = *(const float2*)(q8p + c1);
            float a, b, ah, bh_;
            a = v00.x * 0.125f; b = v00.y * 0.125f; ah = bf16_round(a); bh_ = bf16_round(b);
            qh[ks][0] = pack_bf16x2(ah, bh_); ql[ks][0] = pack_bf16x2(a - ah, b - bh_);
            a = v10.x * 0.125f; b = v10.y * 0.125f; ah = bf16_round(a); bh_ = bf16_round(b);
            qh[ks][1] = pack_bf16x2(ah, bh_); ql[ks][1] = pack_bf16x2(a - ah, b - bh_);
            a = v01.x * 0.125f; b = v01.y * 0.125f; ah = bf16_round(a); bh_ = bf16_round(b);
            qh[ks][2] = pack_bf16x2(ah, bh_); ql[ks][2] = pack_bf16x2(a - ah, b - bh_);
            a = v11.x * 0.125f; b = v11.y * 0.125f; ah = bf16_round(a); bh_ = bf16_round(b);
            qh[ks][3] = pack_bf16x2(ah, bh_); ql[ks][3] = pack_bf16x2(a - ah, b - bh_);
        }
    }

    const uint64_t* mrow0 = g_maskbits + (size_t)(r0 + g) * 64;
    const uint64_t* mrow8 = mrow0 + 8 * 64;

    float o[8][4];
#pragma unroll
    for (int nt = 0; nt < 8; nt++)
#pragma unroll
        for (int i = 0; i < 4; i++) o[nt][i] = 0.f;
    float l0 = 0.f, l1 = 0.f;

    // staging: 2048 16B-chunks per buffer -> 8 per thread
    auto preload = [&](int buf, int k0) {
#pragma unroll
        for (int it = 0; it < 8; it++) {
            int ch = tid + it * 256;          // 0..2047
            int arr = ch >> 9;                // 0:Kh 1:Kl 2:Vh 3:Vl
            int rem = ch & 511;
            int row = rem >> 3, c8 = rem & 7;
            uint32_t dst = smb + ((buf * 4 + arr) * ARRSZ + row * SROW + c8 * 8) * 2;
            const __nv_bfloat16* src;
            if (arr == 0)      src = gKh + (size_t)(k0 + row) * DHH + c8 * 8;
            else if (arr == 1) src = gKl + (size_t)(k0 + row) * DHH + c8 * 8;
            else if (arr == 2) src = gVh + (size_t)row * TT + k0 + c8 * 8;
            else               src = gVl + (size_t)row * TT + k0 + c8 * 8;
            cpa16(dst, src);
        }
        cpa_commit();
    };

    preload(0, 0);

    for (int kt = 0; kt < TT / 64; kt++) {
        const int buf = kt & 1;
        __syncthreads();                      // everyone done reading buf^1 (tile kt-1)
        if (kt + 1 < TT / 64) { preload(buf ^ 1, (kt + 1) * 64); cpa_wait<1>(); }
        else                  { cpa_wait<0>(); }
        __syncthreads();                      // tile kt visible to all

        const uint32_t bKh = smb + (buf * 4 + 0) * ARRSZ * 2 + lane_off;
        const uint32_t bKl = smb + (buf * 4 + 1) * ARRSZ * 2 + lane_off;
        const uint32_t bVh = smb + (buf * 4 + 2) * ARRSZ * 2 + lane_off;
        const uint32_t bVl = smb + (buf * 4 + 3) * ARRSZ * 2 + lane_off;

        // ---- S = Q K^T  (hi*hi + lo*hi + hi*lo) ----
        float s[8][4];
#pragma unroll
        for (int nt = 0; nt < 8; nt++)
#pragma unroll
            for (int i = 0; i < 4; i++) s[nt][i] = 0.f;

#pragma unroll
        for (int p = 0; p < 4; p++) {
#pragma unroll
            for (int ks = 0; ks < 4; ks++) {
                uint32_t off = (uint32_t)(p * 16 * SROW + ks * 16) * 2;
                uint32_t kh[4], kl[4];
                ldsm4(kh, bKh + off);
                ldsm4(kl, bKl + off);
                mma16816(s[2 * p],     qh[ks], kh[0], kh[1]);
                mma16816(s[2 * p],     ql[ks], kh[0], kh[1]);
                mma16816(s[2 * p],     qh[ks], kl[0], kl[1]);
                mma16816(s[2 * p + 1], qh[ks], kh[2], kh[3]);
                mma16816(s[2 * p + 1], ql[ks], kh[2], kh[3]);
                mma16816(s[2 * p + 1], qh[ks], kl[2], kl[3]);
            }
        }

        // ---- mask + exp + repack P as A-fragments (hi/lo) ----
        const uint64_t m0 = mrow0[kt];
        const uint64_t m8 = mrow8[kt];
        uint32_t pah[4][4], pal[4][4];
#pragma unroll
        for (int nt = 0; nt < 8; nt++) {
            int cb = nt * 8 + tg * 2;
            float p0 = ((m0 >> cb) & 1ull)       ? __expf(s[nt][0]) : 0.f;
            float p1 = ((m0 >> (cb + 1)) & 1ull) ? __expf(s[nt][1]) : 0.f;
            float p2 = ((m8 >> cb) & 1ull)       ? __expf(s[nt][2]) : 0.f;
            float p3 = ((m8 >> (cb + 1)) & 1ull) ? __expf(s[nt][3]) : 0.f;
            l0 += p0 + p1;
            l1 += p2 + p3;
            float h0 = bf16_round(p0), h1 = bf16_round(p1);
            float h2 = bf16_round(p2), h3 = bf16_round(p3);
            int ks = nt >> 1;
            int hi = (nt & 1) ? 2 : 0;
            pah[ks][hi]     = pack_bf16x2(h0, h1);
            pah[ks][hi + 1] = pack_bf16x2(h2, h3);
            pal[ks][hi]     = pack_bf16x2(p0 - h0, p1 - h1);
            pal[ks][hi + 1] = pack_bf16x2(p2 - h2, p3 - h3);
        }

        // ---- O += P V  (hi*hi + lo*hi + hi*lo) ----
#pragma unroll
        for (int p = 0; p < 4; p++) {
#pragma unroll
            for (int ks = 0; ks < 4; ks++) {
                uint32_t off = (uint32_t)(p * 16 * SROW + ks * 16) * 2;
                uint32_t vh[4], vl[4];
                ldsm4(vh, bVh + off);
                ldsm4(vl, bVl + off);
                mma16816(o[2 * p],     pah[ks], vh[0], vh[1]);
                mma16816(o[2 * p],     pal[ks], vh[0], vh[1]);
                mma16816(o[2 * p],     pah[ks], vl[0], vl[1]);
                mma16816(o[2 * p + 1], pah[ks], vh[2], vh[3]);
                mma16816(o[2 * p + 1], pal[ks], vh[2], vh[3]);
                mma16816(o[2 * p + 1], pah[ks], vl[2], vl[3]);
            }
        }
    }

    // ---- epilogue: reduce l, normalize, split, store packed (b,t,D) ----
    l0 += __shfl_xor_sync(0xffffffffu, l0, 1);
    l0 += __shfl_xor_sync(0xffffffffu, l0, 2);
    l1 += __shfl_xor_sync(0xffffffffu, l1, 1);
    l1 += __shfl_xor_sync(0xffffffffu, l1, 2);
    float inv0 = 1.f / l0, inv1 = 1.f / l1;

    const int b = bh >> 3, h = bh & 7;
    size_t base0 = ((size_t)b * TT + (r0 + g)) * DD + h * DHH;
    size_t base8 = base0 + (size_t)8 * DD;
#pragma unroll
    for (int nt = 0; nt < 8; nt++) {
        int c = nt * 8 + tg * 2;
        float v0 = o[nt][0] * inv0, v1 = o[nt][1] * inv0;
        float v2 = o[nt][2] * inv1, v3 = o[nt][3] * inv1;
        float h0 = bf16_round(v0), h1 = bf16_round(v1);
        float h2 = bf16_round(v2), h3 = bf16_round(v3);
        *(uint32_t*)&g_Oh[base0 + c] = pack_bf16x2(h0, h1);
        *(uint32_t*)&g_Ol[base0 + c] = pack_bf16x2(v0 - h0, v1 - h1);
        *(uint32_t*)&g_Oh[base8 + c] = pack_bf16x2(h2, h3);
        *(uint32_t*)&g_Ol[base8 + c] = pack_bf16x2(v2 - h2, v3 - h3);
    }
}

// ---------------------------------------------------------------------------
// Launch.  Inputs identified BY SIZE.
// ---------------------------------------------------------------------------
extern "C" void kernel_launch(void* const* d_in, const int* in_sizes, int n_in,
                              void* d_out, int out_size)
{
    const float* x = nullptr;
    const float* Ws[4] = {nullptr, nullptr, nullptr, nullptr};
    const float* bs[4] = {nullptr, nullptr, nullptr, nullptr};
    const void*  mask = nullptr;
    int wc = 0, bc = 0;
    for (int i = 0; i < n_in; i++) {
        int sz = in_sizes[i];
        if (sz == TT * TT)            mask = d_in[i];
        else if (sz == MTOT * DD)     x = (const float*)d_in[i];
        else if (sz == DD * DD)       { if (wc < 4) Ws[wc++] = (const float*)d_in[i]; }
        else if (sz == DD)            { if (bc < 4) bs[bc++] = (const float*)d_in[i]; }
    }
    float* out = (float*)d_out;

    cudaFuncSetAttribute(gemm_qkv_mma, cudaFuncAttributeMaxDynamicSharedMemorySize, GEMM_SMEM);
    cudaFuncSetAttribute(gemm_out_mma, cudaFuncAttributeMaxDynamicSharedMemorySize, GEMM_SMEM);
    cudaFuncSetAttribute(flash_attn_mma, cudaFuncAttributeMaxDynamicSharedMemorySize, FLASH_SMEM);

    detect_mask_kernel<<<1, 32>>>((const uint32_t*)mask);
    pack_mask_kernel<<<1024, 256>>>(mask);
    split_x_kernel<<<MTOT * DD / 1024, 256>>>(x);
    split_w_kernel<<<dim3(WSZ / 1024, 4), 256>>>(Ws[0], Ws[1], Ws[2], Ws[3]);
    gemm_qkv_mma<<<dim3(DD / 64, MTOT / 128, 3), 256, GEMM_SMEM>>>(bs[0], bs[1], bs[2]);
    flash_attn_mma<<<dim3(BB * HH, TT / 128), 256, FLASH_SMEM>>>(0);
    gemm_out_mma<<<dim3(DD / 64, MTOT / 128), 256, GEMM_SMEM>>>(bs[3], out);
}